// round 6
// baseline (speedup 1.0000x reference)
#include <cuda_runtime.h>
#include <math.h>

#define BATCH 4096
#define HLEN  200
#define XD    384
#define H1    200
#define H1P   256     // padded stride for gemm1 partials
#define H2    80
#define BN_EPS 1e-5f
#define RPB   8       // rows per embed CTA

// ---------------- device scratch (static allocation only) ----------------
__device__ float g_x[BATCH * XD];        // concat(u, it, pooled)
__device__ float g_p0[BATCH * H1P];      // gemm1 partial, k-split 0
__device__ float g_p1[BATCH * H1P];      // gemm1 partial, k-split 1
__device__ float g_sum[XD];              // zeroed; finalize resets after use
__device__ float g_sumsq[XD];
__device__ float g_scale[XD];
__device__ float g_shift[XD];
__device__ int   g_first_inactive = BATCH;  // finalize resets after use

// ---------------- kernels ----------------

// outer-break semantics: first row b with history[b,0]==0 deactivates rows >= b
__global__ void scan_kernel(const int* __restrict__ history) {
    int b = blockIdx.x * blockDim.x + threadIdx.x;
    if (b < BATCH && history[b * HLEN] == 0) atomicMin(&g_first_inactive, b);
}

// warp-per-row embedding gather + pool, fused BN partial sums.
__global__ void embed_kernel(const int* __restrict__ user,
                             const int* __restrict__ item,
                             const int* __restrict__ history,
                             const int* __restrict__ cate_list,
                             const float* __restrict__ uW,   // [100000,128]
                             const float* __restrict__ iW,   // [100000,64]
                             const float* __restrict__ cW) { // [1000,64]
    __shared__ int   ids[RPB][HLEN];
    __shared__ float sx[RPB][XD];     // per-row x values for BN reduction

    int b0  = blockIdx.x * RPB;
    int tid = threadIdx.x;

    for (int i = tid; i < RPB * HLEN; i += 256)
        ids[i / HLEN][i % HLEN] = history[b0 * HLEN + i];
    __syncthreads();

    int w = tid >> 5, lane = tid & 31;
    int b = b0 + w;

    // first-zero prefix length via ballot over 32-chunks
    int n = HLEN;
    #pragma unroll
    for (int c = 0; c < (HLEN + 31) / 32; c++) {
        int idx = c * 32 + lane;
        int v = (idx < HLEN) ? ids[w][idx] : 1;
        unsigned m = __ballot_sync(0xffffffffu, v == 0);
        if (m) { n = c * 32 + __ffs(m) - 1; break; }
    }

    int ne = (b < g_first_inactive) ? n : 0;
    float inv_cnt = 1.0f / (float)(ne > 0 ? ne : 1);

    int half = lane >> 4;           // 0 = item half, 1 = cate half
    int q    = lane & 15;           // float4 index within the 64-dim half
    const float4* iW4 = (const float4*)iW;
    const float4* cW4 = (const float4*)cW;

    float4 acc = make_float4(0.f, 0.f, 0.f, 0.f);
    #pragma unroll 8
    for (int l = 0; l < ne; l++) {
        int id  = ids[w][l];
        int rid = half ? __ldg(&cate_list[id]) : id;
        const float4* tab = half ? cW4 : iW4;
        float4 v = __ldg(&tab[rid * 16 + q]);
        acc.x += v.x; acc.y += v.y; acc.z += v.z; acc.w += v.w;
    }
    float4 p = make_float4(acc.x * inv_cnt, acc.y * inv_cnt,
                           acc.z * inv_cnt, acc.w * inv_cnt);

    // user + item embeddings
    float4 uv = __ldg(&((const float4*)uW)[user[b] * 32 + lane]);
    int iid  = item[b];
    int rid2 = half ? __ldg(&cate_list[iid]) : iid;
    const float4* tab2 = half ? cW4 : iW4;
    float4 itv = __ldg(&tab2[rid2 * 16 + q]);

    float4* xr = (float4*)&g_x[b * XD];
    xr[lane]      = uv;
    xr[32 + lane] = itv;
    xr[64 + lane] = p;
    float4* sxr = (float4*)sx[w];
    sxr[lane]      = uv;
    sxr[32 + lane] = itv;
    sxr[64 + lane] = p;
    __syncthreads();

    // per-CTA reduce over 8 rows, then RED.ADD to global BN accumulators
    for (int f = tid; f < XD; f += 256) {
        float s1 = 0.f, s2 = 0.f;
        #pragma unroll
        for (int r = 0; r < RPB; r++) {
            float v = sx[r][f];
            s1 += v; s2 += v * v;
        }
        atomicAdd(&g_sum[f], s1);
        atomicAdd(&g_sumsq[f], s2);
    }
}

// compute BN scale/shift and self-reset accumulators for the next replay
__global__ void finalize_kernel(const float* __restrict__ gamma,
                                const float* __restrict__ beta) {
    int f = threadIdx.x;
    const float invN = 1.f / (float)BATCH;
    float mean = g_sum[f] * invN;
    float var  = g_sumsq[f] * invN - mean * mean;
    float inv  = rsqrtf(var + BN_EPS);
    float sc   = gamma[f] * inv;
    g_scale[f] = sc;
    g_shift[f] = beta[f] - mean * sc;
    g_sum[f]   = 0.f;
    g_sumsq[f] = 0.f;
    if (f == 0) g_first_inactive = BATCH;
}

// partial_z = BN(x)[:, ks:ks+192] @ W1[:, ks:ks+192]^T   (no bias/prelu here)
// M=4096 N=200(pad 256) split-K=2. BM=128 BN=64 BK=16, 256 threads, 8x4.
// Double-buffered smem, reg prefetch, one barrier per K-iter.
// grid = (32, 4, 2); ~2 CTAs/SM -> 16 warps for latency hiding.
__global__ void __launch_bounds__(256, 2)
gemm1_kernel(const float* __restrict__ W1) {
    __shared__ float As[2][16][132];
    __shared__ float Bs[2][16][68];
    __shared__ float ss[XD], sh[XD];

    int m0 = blockIdx.x * 128;
    int n0 = blockIdx.y * 64;
    int ks = blockIdx.z * 192;
    float* gp = blockIdx.z ? g_p1 : g_p0;

    int tid = threadIdx.x;
    int tx = tid >> 4;        // 0..15 -> n-group (4 cols each)
    int ty = tid & 15;        // 0..15 -> m-group (8 rows each)
    bool nactive = (n0 + tx * 4) < H1;

    int lmA0 = tid >> 2;                 // rows 0..63
    int lmA1 = (tid + 256) >> 2;         // rows 64..127
    int lkq  = (tid & 3) * 4;            // k-quad within BK
    int lnB  = tid >> 2;                 // n within tile
    int gnB  = n0 + lnB;

    for (int i = tid; i < XD; i += 256) { ss[i] = g_scale[i]; sh[i] = g_shift[i]; }

    float acc[8][4];
    #pragma unroll
    for (int i = 0; i < 8; i++)
        #pragma unroll
        for (int j = 0; j < 4; j++) acc[i][j] = 0.f;

    // prologue: tile 0 -> regs -> smem buf 0
    float4 pa0 = *(const float4*)&g_x[(m0 + lmA0) * XD + ks + lkq];
    float4 pa1 = *(const float4*)&g_x[(m0 + lmA1) * XD + ks + lkq];
    float4 pb  = (gnB < H1) ? *(const float4*)&W1[gnB * XD + ks + lkq]
                            : make_float4(0.f, 0.f, 0.f, 0.f);
    __syncthreads();   // ss/sh ready
    {
        int kg = ks + lkq;
        As[0][lkq + 0][lmA0] = pa0.x * ss[kg + 0] + sh[kg + 0];
        As[0][lkq + 1][lmA0] = pa0.y * ss[kg + 1] + sh[kg + 1];
        As[0][lkq + 2][lmA0] = pa0.z * ss[kg + 2] + sh[kg + 2];
        As[0][lkq + 3][lmA0] = pa0.w * ss[kg + 3] + sh[kg + 3];
        As[0][lkq + 0][lmA1] = pa1.x * ss[kg + 0] + sh[kg + 0];
        As[0][lkq + 1][lmA1] = pa1.y * ss[kg + 1] + sh[kg + 1];
        As[0][lkq + 2][lmA1] = pa1.z * ss[kg + 2] + sh[kg + 2];
        As[0][lkq + 3][lmA1] = pa1.w * ss[kg + 3] + sh[kg + 3];
        Bs[0][lkq + 0][lnB] = pb.x;
        Bs[0][lkq + 1][lnB] = pb.y;
        Bs[0][lkq + 2][lnB] = pb.z;
        Bs[0][lkq + 3][lnB] = pb.w;
    }
    __syncthreads();

    #pragma unroll 1
    for (int it = 0; it < 12; it++) {
        int cur = it & 1;
        float4 na0, na1, nb;
        int k0n = ks + (it + 1) * 16;
        if (it < 11) {
            na0 = *(const float4*)&g_x[(m0 + lmA0) * XD + k0n + lkq];
            na1 = *(const float4*)&g_x[(m0 + lmA1) * XD + k0n + lkq];
            nb  = (gnB < H1) ? *(const float4*)&W1[gnB * XD + k0n + lkq]
                             : make_float4(0.f, 0.f, 0.f, 0.f);
        }
        if (nactive) {
            #pragma unroll
            for (int kk = 0; kk < 16; kk++) {
                float4 t0 = *(const float4*)&As[cur][kk][ty * 8];
                float4 t1 = *(const float4*)&As[cur][kk][ty * 8 + 4];
                float4 tb = *(const float4*)&Bs[cur][kk][tx * 4];
                float a[8] = {t0.x, t0.y, t0.z, t0.w, t1.x, t1.y, t1.z, t1.w};
                float bb[4] = {tb.x, tb.y, tb.z, tb.w};
                #pragma unroll
                for (int i = 0; i < 8; i++)
                    #pragma unroll
                    for (int j = 0; j < 4; j++) acc[i][j] += a[i] * bb[j];
            }
        }
        if (it < 11) {
            int nxt = cur ^ 1;
            int kg = k0n + lkq;
            As[nxt][lkq + 0][lmA0] = na0.x * ss[kg + 0] + sh[kg + 0];
            As[nxt][lkq + 1][lmA0] = na0.y * ss[kg + 1] + sh[kg + 1];
            As[nxt][lkq + 2][lmA0] = na0.z * ss[kg + 2] + sh[kg + 2];
            As[nxt][lkq + 3][lmA0] = na0.w * ss[kg + 3] + sh[kg + 3];
            As[nxt][lkq + 0][lmA1] = na1.x * ss[kg + 0] + sh[kg + 0];
            As[nxt][lkq + 1][lmA1] = na1.y * ss[kg + 1] + sh[kg + 1];
            As[nxt][lkq + 2][lmA1] = na1.z * ss[kg + 2] + sh[kg + 2];
            As[nxt][lkq + 3][lmA1] = na1.w * ss[kg + 3] + sh[kg + 3];
            Bs[nxt][lkq + 0][lnB] = nb.x;
            Bs[nxt][lkq + 1][lnB] = nb.y;
            Bs[nxt][lkq + 2][lnB] = nb.z;
            Bs[nxt][lkq + 3][lnB] = nb.w;
        }
        __syncthreads();
    }

    if (nactive) {
        #pragma unroll
        for (int j = 0; j < 4; j++) {
            int gn = n0 + tx * 4 + j;
            if (gn < H1) {
                #pragma unroll
                for (int i = 0; i < 8; i++) {
                    int gm = m0 + ty * 8 + i;
                    gp[gm * H1P + gn] = acc[i][j];
                }
            }
        }
    }
}

// y2 = prelu(y1 @ W2^T + b2); logits = y2 @ W3^T + b3; softmax — fused.
// A-loader reconstructs y1 = prelu(p0 + p1 + b1) from gemm1's k-split partials.
// M=4096 N=80 K=200; BM=64 BN=80 BK=8, 256 threads, 4x5, double-buffered.
__global__ void gemm2_out_kernel(const float* __restrict__ b1,
                                 const float* __restrict__ a1p,
                                 const float* __restrict__ W2,
                                 const float* __restrict__ b2,
                                 const float* __restrict__ a2p,
                                 const float* __restrict__ W3,
                                 const float* __restrict__ b3,
                                 float* __restrict__ out) {
    __shared__ float As[2][8][68];
    __shared__ float Bs[2][8][84];
    __shared__ float sy[64][81];
    __shared__ float sw3[2 * H2];
    __shared__ float sb1[H1];

    int m0 = blockIdx.x * 64;
    int tid = threadIdx.x;
    int tx = tid & 15, ty = tid >> 4;     // tx -> n (5 each), ty -> m (4 each)
    int lk2 = (tid & 3) * 2, lm = tid >> 2;       // A loader: float2 along k
    int bn = tid >> 1, bq = (tid & 1) * 4;        // B loader: threads<160 load float4

    if (tid < 2 * H2) sw3[tid] = W3[tid];
    if (tid < H1) sb1[tid] = b1[tid];
    float alpha1 = __ldg(a1p);

    float acc[4][5];
    #pragma unroll
    for (int i = 0; i < 4; i++)
        #pragma unroll
        for (int j = 0; j < 5; j++) acc[i][j] = 0.f;

    // prologue
    int arow = (m0 + lm) * H1P;
    float2 q0 = *(const float2*)&g_p0[arow + lk2];
    float2 q1 = *(const float2*)&g_p1[arow + lk2];
    float4 pb = (tid < 160) ? *(const float4*)&W2[bn * H1 + bq]
                            : make_float4(0.f, 0.f, 0.f, 0.f);
    __syncthreads();   // sb1 ready
    {
        float z0 = q0.x + q1.x + sb1[lk2 + 0];
        float z1 = q0.y + q1.y + sb1[lk2 + 1];
        As[0][lk2 + 0][lm] = (z0 >= 0.f) ? z0 : alpha1 * z0;
        As[0][lk2 + 1][lm] = (z1 >= 0.f) ? z1 : alpha1 * z1;
    }
    if (tid < 160) {
        Bs[0][bq + 0][bn] = pb.x; Bs[0][bq + 1][bn] = pb.y;
        Bs[0][bq + 2][bn] = pb.z; Bs[0][bq + 3][bn] = pb.w;
    }
    __syncthreads();

    #pragma unroll 1
    for (int it = 0; it < 25; it++) {
        int cur = it & 1;
        float2 n0v, n1v; float4 nb;
        int k0n = (it + 1) * 8;
        if (it < 24) {
            n0v = *(const float2*)&g_p0[arow + k0n + lk2];
            n1v = *(const float2*)&g_p1[arow + k0n + lk2];
            if (tid < 160) nb = *(const float4*)&W2[bn * H1 + k0n + bq];
        }
        #pragma unroll
        for (int kk = 0; kk < 8; kk++) {
            float4 ta = *(const float4*)&As[cur][kk][ty * 4];
            float a[4] = {ta.x, ta.y, ta.z, ta.w};
            float bb[5];
            #pragma unroll
            for (int j = 0; j < 5; j++) bb[j] = Bs[cur][kk][tx * 5 + j];
            #pragma unroll
            for (int i = 0; i < 4; i++)
                #pragma unroll
                for (int j = 0; j < 5; j++) acc[i][j] += a[i] * bb[j];
        }
        if (it < 24) {
            int nxt = cur ^ 1;
            float z0 = n0v.x + n1v.x + sb1[k0n + lk2 + 0];
            float z1 = n0v.y + n1v.y + sb1[k0n + lk2 + 1];
            As[nxt][lk2 + 0][lm] = (z0 >= 0.f) ? z0 : alpha1 * z0;
            As[nxt][lk2 + 1][lm] = (z1 >= 0.f) ? z1 : alpha1 * z1;
            if (tid < 160) {
                Bs[nxt][bq + 0][bn] = nb.x; Bs[nxt][bq + 1][bn] = nb.y;
                Bs[nxt][bq + 2][bn] = nb.z; Bs[nxt][bq + 3][bn] = nb.w;
            }
        }
        __syncthreads();
    }

    float alpha = a2p[0];
    #pragma unroll
    for (int i = 0; i < 4; i++)
        #pragma unroll
        for (int j = 0; j < 5; j++) {
            float v = acc[i][j] + b2[tx * 5 + j];
            v = (v >= 0.f) ? v : alpha * v;
            sy[ty * 4 + i][tx * 5 + j] = v;
        }
    __syncthreads();

    // logits + softmax: 4 threads per row, 20 dims each, shuffle-combine
    int row = tid >> 2, part = tid & 3;
    float s0 = 0.f, s1 = 0.f;
    int kbase = part * 20;
    #pragma unroll
    for (int k = 0; k < 20; k++) {
        float v = sy[row][kbase + k];
        s0 += v * sw3[kbase + k];
        s1 += v * sw3[H2 + kbase + k];
    }
    s0 += __shfl_down_sync(0xffffffffu, s0, 2, 4);
    s0 += __shfl_down_sync(0xffffffffu, s0, 1, 4);
    s1 += __shfl_down_sync(0xffffffffu, s1, 2, 4);
    s1 += __shfl_down_sync(0xffffffffu, s1, 1, 4);
    if (part == 0) {
        float l0 = s0 + b3[0], l1 = s1 + b3[1];
        float m = fmaxf(l0, l1);
        float e0 = expf(l0 - m), e1 = expf(l1 - m);
        float inv = 1.f / (e0 + e1);
        out[(m0 + row) * 2 + 0] = e0 * inv;
        out[(m0 + row) * 2 + 1] = e1 * inv;
    }
}

// ---------------- launch ----------------
extern "C" void kernel_launch(void* const* d_in, const int* in_sizes, int n_in,
                              void* d_out, int out_size) {
    const int*   user      = (const int*)d_in[0];
    const int*   item      = (const int*)d_in[1];
    const int*   history   = (const int*)d_in[2];
    // d_in[3] = length (unused; semantics derived from history zeros)
    const int*   cate_list = (const int*)d_in[4];
    const float* uW        = (const float*)d_in[5];
    const float* iW        = (const float*)d_in[6];
    const float* cW        = (const float*)d_in[7];
    const float* gamma     = (const float*)d_in[8];
    const float* beta      = (const float*)d_in[9];
    const float* W1        = (const float*)d_in[10];
    const float* b1        = (const float*)d_in[11];
    const float* a1        = (const float*)d_in[12];
    const float* W2        = (const float*)d_in[13];
    const float* b2        = (const float*)d_in[14];
    const float* a2        = (const float*)d_in[15];
    const float* W3        = (const float*)d_in[16];
    const float* b3        = (const float*)d_in[17];
    float* out = (float*)d_out;

    scan_kernel<<<16, 256>>>(history);
    embed_kernel<<<BATCH / RPB, 256>>>(user, item, history, cate_list, uW, iW, cW);
    finalize_kernel<<<1, 384>>>(gamma, beta);
    dim3 g1(BATCH / 128, 4, 2);
    gemm1_kernel<<<g1, 256>>>(W1);
    gemm2_out_kernel<<<BATCH / 64, 256>>>(b1, a1, W2, b2, a2, W3, b3, out);
}

// round 7
// speedup vs baseline: 1.0883x; 1.0883x over previous
#include <cuda_runtime.h>
#include <math.h>
#include <stdint.h>

#define BATCH 4096
#define HLEN  200
#define XD    384
#define H1    200
#define H2    80
#define BN_EPS 1e-5f
#define RPB   8       // rows per embed CTA

// ---------------- device scratch (static allocation only) ----------------
__device__ float g_x[BATCH * XD];        // concat(u, it, pooled)
__device__ float g_y1[BATCH * H1];
__device__ float g_sum[XD];              // zeroed; finalize resets after use
__device__ float g_sumsq[XD];
__device__ float g_scale[XD];
__device__ float g_shift[XD];
__device__ int   g_first_inactive = BATCH;  // finalize resets after use

// ---------------- helpers ----------------
__device__ __forceinline__ uint32_t f2tf32(float f) {
    uint32_t r;
    asm("cvt.rna.tf32.f32 %0, %1;" : "=r"(r) : "f"(f));
    return r;
}
// split f into tf32 hi + tf32(lo) packed as uint2
__device__ __forceinline__ uint2 tf32_split(float f) {
    uint32_t hi = f2tf32(f);
    float lo = f - __uint_as_float(hi);
    return make_uint2(hi, f2tf32(lo));
}
__device__ __forceinline__ void mma_tf32(float4& d,
                                         uint32_t a0, uint32_t a1,
                                         uint32_t a2, uint32_t a3,
                                         uint32_t b0, uint32_t b1) {
    asm volatile(
        "mma.sync.aligned.m16n8k8.row.col.f32.tf32.tf32.f32 "
        "{%0,%1,%2,%3}, {%4,%5,%6,%7}, {%8,%9}, {%0,%1,%2,%3};"
        : "+f"(d.x), "+f"(d.y), "+f"(d.z), "+f"(d.w)
        : "r"(a0), "r"(a1), "r"(a2), "r"(a3), "r"(b0), "r"(b1));
}

// ---------------- kernels ----------------

// outer-break semantics: first row b with history[b,0]==0 deactivates rows >= b
__global__ void scan_kernel(const int* __restrict__ history) {
    int b = blockIdx.x * blockDim.x + threadIdx.x;
    if (b < BATCH && history[b * HLEN] == 0) atomicMin(&g_first_inactive, b);
}

// warp-per-row embedding gather + pool, fused BN partial sums.
__global__ void embed_kernel(const int* __restrict__ user,
                             const int* __restrict__ item,
                             const int* __restrict__ history,
                             const int* __restrict__ cate_list,
                             const float* __restrict__ uW,   // [100000,128]
                             const float* __restrict__ iW,   // [100000,64]
                             const float* __restrict__ cW) { // [1000,64]
    __shared__ int   ids[RPB][HLEN];
    __shared__ float sx[RPB][XD];     // per-row x values for BN reduction

    int b0  = blockIdx.x * RPB;
    int tid = threadIdx.x;

    for (int i = tid; i < RPB * HLEN; i += 256)
        ids[i / HLEN][i % HLEN] = history[b0 * HLEN + i];
    __syncthreads();

    int w = tid >> 5, lane = tid & 31;
    int b = b0 + w;

    // first-zero prefix length via ballot over 32-chunks
    int n = HLEN;
    #pragma unroll
    for (int c = 0; c < (HLEN + 31) / 32; c++) {
        int idx = c * 32 + lane;
        int v = (idx < HLEN) ? ids[w][idx] : 1;
        unsigned m = __ballot_sync(0xffffffffu, v == 0);
        if (m) { n = c * 32 + __ffs(m) - 1; break; }
    }

    int ne = (b < g_first_inactive) ? n : 0;
    float inv_cnt = 1.0f / (float)(ne > 0 ? ne : 1);

    int half = lane >> 4;           // 0 = item half, 1 = cate half
    int q    = lane & 15;           // float4 index within the 64-dim half
    const float4* iW4 = (const float4*)iW;
    const float4* cW4 = (const float4*)cW;

    float4 acc = make_float4(0.f, 0.f, 0.f, 0.f);
    #pragma unroll 8
    for (int l = 0; l < ne; l++) {
        int id  = ids[w][l];
        int rid = half ? __ldg(&cate_list[id]) : id;
        const float4* tab = half ? cW4 : iW4;
        float4 v = __ldg(&tab[rid * 16 + q]);
        acc.x += v.x; acc.y += v.y; acc.z += v.z; acc.w += v.w;
    }
    float4 p = make_float4(acc.x * inv_cnt, acc.y * inv_cnt,
                           acc.z * inv_cnt, acc.w * inv_cnt);

    // user + item embeddings
    float4 uv = __ldg(&((const float4*)uW)[user[b] * 32 + lane]);
    int iid  = item[b];
    int rid2 = half ? __ldg(&cate_list[iid]) : iid;
    const float4* tab2 = half ? cW4 : iW4;
    float4 itv = __ldg(&tab2[rid2 * 16 + q]);

    float4* xr = (float4*)&g_x[b * XD];
    xr[lane]      = uv;
    xr[32 + lane] = itv;
    xr[64 + lane] = p;
    float4* sxr = (float4*)sx[w];
    sxr[lane]      = uv;
    sxr[32 + lane] = itv;
    sxr[64 + lane] = p;
    __syncthreads();

    // per-CTA reduce over 8 rows, then RED.ADD to global BN accumulators
    for (int f = tid; f < XD; f += 256) {
        float s1 = 0.f, s2 = 0.f;
        #pragma unroll
        for (int r = 0; r < RPB; r++) {
            float v = sx[r][f];
            s1 += v; s2 += v * v;
        }
        atomicAdd(&g_sum[f], s1);
        atomicAdd(&g_sumsq[f], s2);
    }
}

// compute BN scale/shift and self-reset accumulators for the next replay
__global__ void finalize_kernel(const float* __restrict__ gamma,
                                const float* __restrict__ beta) {
    int f = threadIdx.x;
    const float invN = 1.f / (float)BATCH;
    float mean = g_sum[f] * invN;
    float var  = g_sumsq[f] * invN - mean * mean;
    float inv  = rsqrtf(var + BN_EPS);
    float sc   = gamma[f] * inv;
    g_scale[f] = sc;
    g_shift[f] = beta[f] - mean * sc;
    g_sum[f]   = 0.f;
    g_sumsq[f] = 0.f;
    if (f == 0) g_first_inactive = BATCH;
}

// y1 = prelu(BN(x) @ W1^T + b1) via tf32 tensor-core mma with hi/lo
// error compensation (3 products). M=4096 N=200(pad 256) K=384.
// CTA: BM=128 BN=64, 8 warps (4m x 2n), warp tile 32x32, BK=8, 2-stage smem.
__global__ void __launch_bounds__(256)
gemm1_kernel(const float* __restrict__ W1,
             const float* __restrict__ b1,
             const float* __restrict__ a1p) {
    __shared__ uint2 As[2][8][132];   // (tf32 hi, tf32 lo), [k][m]
    __shared__ uint2 Bs[2][8][68];    // [k][n]
    __shared__ float ss[XD], sh[XD];

    int m0 = blockIdx.x * 128;
    int n0 = blockIdx.y * 64;
    int tid  = threadIdx.x;
    int lane = tid & 31, wid = tid >> 5;
    int g = lane >> 2, tig = lane & 3;
    int wm = wid & 3;        // m-warp: 32 rows each
    int wn = wid >> 2;       // n-warp: 32 cols each

    // loaders
    int lm  = tid >> 1;            // A: m row 0..127
    int lkq = (tid & 1) * 4;       // A/B: k-quad
    int bn  = tid >> 1;            // B (tid<128): n 0..63
    int gn  = n0 + bn;

    for (int i = tid; i < XD; i += 256) { ss[i] = g_scale[i]; sh[i] = g_shift[i]; }

    float4 acc[2][4];
    #pragma unroll
    for (int t = 0; t < 2; t++)
        #pragma unroll
        for (int nt = 0; nt < 4; nt++) acc[t][nt] = make_float4(0.f, 0.f, 0.f, 0.f);

    // prologue: k-tile 0 -> regs
    float4 pa = *(const float4*)&g_x[(m0 + lm) * XD + lkq];
    float4 pb = make_float4(0.f, 0.f, 0.f, 0.f);
    if (tid < 128 && gn < H1) pb = *(const float4*)&W1[gn * XD + lkq];
    __syncthreads();   // ss/sh ready
    {
        float fa[4] = {pa.x, pa.y, pa.z, pa.w};
        #pragma unroll
        for (int j = 0; j < 4; j++)
            As[0][lkq + j][lm] = tf32_split(fa[j] * ss[lkq + j] + sh[lkq + j]);
        if (tid < 128) {
            float fb[4] = {pb.x, pb.y, pb.z, pb.w};
            #pragma unroll
            for (int j = 0; j < 4; j++)
                Bs[0][lkq + j][bn] = tf32_split(fb[j]);
        }
    }
    __syncthreads();

    #pragma unroll 1
    for (int it = 0; it < 48; it++) {
        int cur = it & 1;
        float4 na, nb;
        int k0n = (it + 1) * 8;
        if (it < 47) {
            na = *(const float4*)&g_x[(m0 + lm) * XD + k0n + lkq];
            nb = make_float4(0.f, 0.f, 0.f, 0.f);
            if (tid < 128 && gn < H1) nb = *(const float4*)&W1[gn * XD + k0n + lkq];
        }

        // fragments: A row-major m16k8, B col-major k8n8
        uint2 af[2][4];
        #pragma unroll
        for (int t = 0; t < 2; t++) {
            int mb = wm * 32 + t * 16;
            af[t][0] = As[cur][tig][mb + g];
            af[t][1] = As[cur][tig][mb + g + 8];
            af[t][2] = As[cur][tig + 4][mb + g];
            af[t][3] = As[cur][tig + 4][mb + g + 8];
        }
        uint2 bf[4][2];
        #pragma unroll
        for (int nt = 0; nt < 4; nt++) {
            int nb2 = wn * 32 + nt * 8;
            bf[nt][0] = Bs[cur][tig][nb2 + g];
            bf[nt][1] = Bs[cur][tig + 4][nb2 + g];
        }
        #pragma unroll
        for (int t = 0; t < 2; t++)
            #pragma unroll
            for (int nt = 0; nt < 4; nt++) {
                mma_tf32(acc[t][nt], af[t][0].x, af[t][1].x, af[t][2].x, af[t][3].x,
                         bf[nt][0].x, bf[nt][1].x);
                mma_tf32(acc[t][nt], af[t][0].x, af[t][1].x, af[t][2].x, af[t][3].x,
                         bf[nt][0].y, bf[nt][1].y);
                mma_tf32(acc[t][nt], af[t][0].y, af[t][1].y, af[t][2].y, af[t][3].y,
                         bf[nt][0].x, bf[nt][1].x);
            }

        if (it < 47) {
            int nxt = cur ^ 1;
            float fa[4] = {na.x, na.y, na.z, na.w};
            #pragma unroll
            for (int j = 0; j < 4; j++)
                As[nxt][lkq + j][lm] =
                    tf32_split(fa[j] * ss[k0n + lkq + j] + sh[k0n + lkq + j]);
            if (tid < 128) {
                float fb[4] = {nb.x, nb.y, nb.z, nb.w};
                #pragma unroll
                for (int j = 0; j < 4; j++)
                    Bs[nxt][lkq + j][bn] = tf32_split(fb[j]);
            }
        }
        __syncthreads();
    }

    // epilogue: bias + prelu, write y1
    float alpha = __ldg(a1p);
    #pragma unroll
    for (int t = 0; t < 2; t++) {
        int row = m0 + wm * 32 + t * 16 + g;
        #pragma unroll
        for (int nt = 0; nt < 4; nt++) {
            int col = n0 + wn * 32 + nt * 8 + tig * 2;
            if (col < H1) {
                float b0v = __ldg(&b1[col]), b1v = __ldg(&b1[col + 1]);
                float v0 = acc[t][nt].x + b0v;
                float v1 = acc[t][nt].y + b1v;
                float v2 = acc[t][nt].z + b0v;
                float v3 = acc[t][nt].w + b1v;
                v0 = (v0 >= 0.f) ? v0 : alpha * v0;
                v1 = (v1 >= 0.f) ? v1 : alpha * v1;
                v2 = (v2 >= 0.f) ? v2 : alpha * v2;
                v3 = (v3 >= 0.f) ? v3 : alpha * v3;
                *(float2*)&g_y1[row * H1 + col]       = make_float2(v0, v1);
                *(float2*)&g_y1[(row + 8) * H1 + col] = make_float2(v2, v3);
            }
        }
    }
}

// y2 = prelu(y1 @ W2^T + b2); logits = y2 @ W3^T + b3; softmax — fused.
// M=4096 N=80 K=200; BM=64 BN=80 BK=8, 256 threads, 4x5, double-buffered.
__global__ void gemm2_out_kernel(const float* __restrict__ W2,
                                 const float* __restrict__ b2,
                                 const float* __restrict__ a2p,
                                 const float* __restrict__ W3,
                                 const float* __restrict__ b3,
                                 float* __restrict__ out) {
    __shared__ float As[2][8][68];
    __shared__ float Bs[2][8][84];
    __shared__ float sy[64][81];
    __shared__ float sw3[2 * H2];

    int m0 = blockIdx.x * 64;
    int tid = threadIdx.x;
    int tx = tid & 15, ty = tid >> 4;     // tx -> n (5 each), ty -> m (4 each)
    int lk2 = (tid & 3) * 2, lm = tid >> 2;       // A loader: float2 along k
    int bn = tid >> 1, bq = (tid & 1) * 4;        // B loader: threads<160 load float4

    if (tid < 2 * H2) sw3[tid] = W3[tid];

    float acc[4][5];
    #pragma unroll
    for (int i = 0; i < 4; i++)
        #pragma unroll
        for (int j = 0; j < 5; j++) acc[i][j] = 0.f;

    // prologue
    float2 pa = *(const float2*)&g_y1[(m0 + lm) * H1 + lk2];
    float4 pb = (tid < 160) ? *(const float4*)&W2[bn * H1 + bq]
                            : make_float4(0.f, 0.f, 0.f, 0.f);
    As[0][lk2 + 0][lm] = pa.x;
    As[0][lk2 + 1][lm] = pa.y;
    if (tid < 160) {
        Bs[0][bq + 0][bn] = pb.x; Bs[0][bq + 1][bn] = pb.y;
        Bs[0][bq + 2][bn] = pb.z; Bs[0][bq + 3][bn] = pb.w;
    }
    __syncthreads();

    #pragma unroll 1
    for (int it = 0; it < 25; it++) {
        int cur = it & 1;
        float2 na; float4 nb;
        int k0n = (it + 1) * 8;
        if (it < 24) {
            na = *(const float2*)&g_y1[(m0 + lm) * H1 + k0n + lk2];
            if (tid < 160) nb = *(const float4*)&W2[bn * H1 + k0n + bq];
        }
        #pragma unroll
        for (int kk = 0; kk < 8; kk++) {
            float4 ta = *(const float4*)&As[cur][kk][ty * 4];
            float a[4] = {ta.x, ta.y, ta.z, ta.w};
            float bb[5];
            #pragma unroll
            for (int j = 0; j < 5; j++) bb[j] = Bs[cur][kk][tx * 5 + j];
            #pragma unroll
            for (int i = 0; i < 4; i++)
                #pragma unroll
                for (int j = 0; j < 5; j++) acc[i][j] += a[i] * bb[j];
        }
        if (it < 24) {
            int nxt = cur ^ 1;
            As[nxt][lk2 + 0][lm] = na.x;
            As[nxt][lk2 + 1][lm] = na.y;
            if (tid < 160) {
                Bs[nxt][bq + 0][bn] = nb.x; Bs[nxt][bq + 1][bn] = nb.y;
                Bs[nxt][bq + 2][bn] = nb.z; Bs[nxt][bq + 3][bn] = nb.w;
            }
        }
        __syncthreads();
    }

    float alpha = a2p[0];
    #pragma unroll
    for (int i = 0; i < 4; i++)
        #pragma unroll
        for (int j = 0; j < 5; j++) {
            float v = acc[i][j] + b2[tx * 5 + j];
            v = (v >= 0.f) ? v : alpha * v;
            sy[ty * 4 + i][tx * 5 + j] = v;
        }
    __syncthreads();

    // logits + softmax: 4 threads per row, 20 dims each, shuffle-combine
    int row = tid >> 2, part = tid & 3;
    float s0 = 0.f, s1 = 0.f;
    int kbase = part * 20;
    #pragma unroll
    for (int k = 0; k < 20; k++) {
        float v = sy[row][kbase + k];
        s0 += v * sw3[kbase + k];
        s1 += v * sw3[H2 + kbase + k];
    }
    s0 += __shfl_down_sync(0xffffffffu, s0, 2, 4);
    s0 += __shfl_down_sync(0xffffffffu, s0, 1, 4);
    s1 += __shfl_down_sync(0xffffffffu, s1, 2, 4);
    s1 += __shfl_down_sync(0xffffffffu, s1, 1, 4);
    if (part == 0) {
        float l0 = s0 + b3[0], l1 = s1 + b3[1];
        float m = fmaxf(l0, l1);
        float e0 = expf(l0 - m), e1 = expf(l1 - m);
        float inv = 1.f / (e0 + e1);
        out[(m0 + row) * 2 + 0] = e0 * inv;
        out[(m0 + row) * 2 + 1] = e1 * inv;
    }
}

// ---------------- launch ----------------
extern "C" void kernel_launch(void* const* d_in, const int* in_sizes, int n_in,
                              void* d_out, int out_size) {
    const int*   user      = (const int*)d_in[0];
    const int*   item      = (const int*)d_in[1];
    const int*   history   = (const int*)d_in[2];
    // d_in[3] = length (unused; semantics derived from history zeros)
    const int*   cate_list = (const int*)d_in[4];
    const float* uW        = (const float*)d_in[5];
    const float* iW        = (const float*)d_in[6];
    const float* cW        = (const float*)d_in[7];
    const float* gamma     = (const float*)d_in[8];
    const float* beta      = (const float*)d_in[9];
    const float* W1        = (const float*)d_in[10];
    const float* b1        = (const float*)d_in[11];
    const float* a1        = (const float*)d_in[12];
    const float* W2        = (const float*)d_in[13];
    const float* b2        = (const float*)d_in[14];
    const float* a2        = (const float*)d_in[15];
    const float* W3        = (const float*)d_in[16];
    const float* b3        = (const float*)d_in[17];
    float* out = (float*)d_out;

    scan_kernel<<<16, 256>>>(history);
    embed_kernel<<<BATCH / RPB, 256>>>(user, item, history, cate_list, uW, iW, cW);
    finalize_kernel<<<1, 384>>>(gamma, beta);
    dim3 g1(BATCH / 128, 4);
    gemm1_kernel<<<g1, 256>>>(W1, b1, a1);
    gemm2_out_kernel<<<BATCH / 64, 256>>>(W2, b2, a2, W3, b3, out);
}